// round 6
// baseline (speedup 1.0000x reference)
#include <cuda_runtime.h>
#include <cstdint>

#define H      100
#define NBATCH 4096
#define SEQ    512
#define TB     32
#define NBLK   (NBATCH / TB)   // 128
#define NTHREADS 400           // 2 k-groups * (50 hp * 4 bg)

// smem (u64 units):
//   Wp   [100][200]   : Wp[k*200 + hp*4 + ty] = (W[ty*100+2hp][k], W[ty*100+2hp+1][k])
//   Hd   2 x 3200 f32 : h[k][32], double buffered          (3200 u64 total)
//   Rbuf [8][400]     : partial-sum exchange, ulonglong2-tiled (3200 u64)
#define WP_U64 (100 * 200)     // 20000
#define HD_F   (100 * 32)      // 3200 floats per buffer
#define RB_U64 (8 * 400)       // 3200
#define SMEM_BYTES ((WP_U64 + 3200 + RB_U64) * 8)  // 211,200 B

typedef unsigned long long u64;

__device__ __forceinline__ void fma2(u64 &d, u64 a, u64 b) {
    asm("fma.rn.f32x2 %0, %1, %2, %0;" : "+l"(d) : "l"(a), "l"(b));
}
__device__ __forceinline__ void add2(u64 &d, u64 a) {
    asm("add.rn.f32x2 %0, %0, %1;" : "+l"(d) : "l"(a));
}
__device__ __forceinline__ u64 pk(float x, float y) {
    u64 r; asm("mov.b64 %0, {%1, %2};" : "=l"(r) : "f"(x), "f"(y)); return r;
}
__device__ __forceinline__ float2 upk(u64 v) {
    float2 r; asm("mov.b64 {%0, %1}, %2;" : "=f"(r.x), "=f"(r.y) : "l"(v)); return r;
}
__device__ __forceinline__ float tanh_mufu(float v) {
    float r; asm("tanh.approx.f32 %0, %1;" : "=f"(r) : "f"(v)); return r;
}
__device__ __forceinline__ float sig_mufu(float v) {
    return fmaf(0.5f, tanh_mufu(0.5f * v), 0.5f);
}

__global__ void __launch_bounds__(NTHREADS, 1)
lstm_kernel(const float* __restrict__ x,     // [512][4096]
            const float* __restrict__ Wih,   // [400]
            const float* __restrict__ Whh,   // [400][100]
            const float* __restrict__ bih,   // [400]
            const float* __restrict__ bhh,   // [400]
            const float* __restrict__ Wlin,  // [100]
            const float* __restrict__ blin,  // [1]
            float* __restrict__ out)         // [4096]
{
    extern __shared__ u64 sm[];
    u64*   Wp   = sm;                          // [k*200 + hp*4 + ty]
    float* Hd   = (float*)(sm + WP_U64);       // [buf*HD_F + k*32 + b]
    u64*   Rbuf = sm + WP_U64 + 3200;          // [q*400 + wtid*2 + r]

    const int tid  = threadIdx.x;
    const int g    = (tid >= 200);  // k-group: 0 -> k in [0,50), 1 -> [50,100)
    const int wtid = tid - g * 200; // 0..199
    const int hp   = wtid >> 2;     // 0..49  (hidden pair: hu 2hp, 2hp+1)
    const int bg   = wtid & 3;      // 0..3   (batch octet)

    // ---- Stage W_hh: pairs over adjacent hidden units, per gate type ----
    for (int idx = tid; idx < WP_U64; idx += NTHREADS) {
        int k  = idx / 200;
        int q  = idx % 200;
        int ph = q >> 2;
        int ty = q & 3;
        int row0 = ty * 100 + 2 * ph;
        Wp[idx] = pk(Whh[row0 * 100 + k], Whh[(row0 + 1) * 100 + k]);
    }
    for (int idx = tid; idx < 2 * HD_F; idx += NTHREADS)
        Hd[idx] = 0.f;

    // ---- per-thread constants ----
    float bs[2][4], wi[2][4];  // [u][ty], types: 0=i 1=f 2=g 3=o
    #pragma unroll
    for (int u = 0; u < 2; u++) {
        int hu = 2 * hp + u;
        #pragma unroll
        for (int ty = 0; ty < 4; ty++) {
            int j = ty * 100 + hu;
            bs[u][ty] = bih[j] + bhh[j];
            wi[u][ty] = Wih[j];
        }
    }
    float c[2][4];  // cell state for my 4 epilogue batches
    #pragma unroll
    for (int u = 0; u < 2; u++)
        #pragma unroll
        for (int j = 0; j < 4; j++) c[u][j] = 0.f;

    const int kbeg = g * 50;
    const int bbase = blockIdx.x * TB + bg * 8 + g * 4;  // my 4 epilogue batches
    __syncthreads();

    // ---- recurrence over 512 steps ----
    for (int t = 0; t < SEQ; t++) {
        const float* hcur = Hd + ((t & 1) ? HD_F : 0);
        float*       hnxt = Hd + ((t & 1) ? 0 : HD_F);

        float4 xv = *(const float4*)(x + (size_t)t * NBATCH + bbase);

        u64 acc[4][8];  // acc[ty][b]: f32x2 over (hu 2hp, 2hp+1), partial over my k-half
        #pragma unroll
        for (int ty = 0; ty < 4; ty++)
            #pragma unroll
            for (int b = 0; b < 8; b++) acc[ty][b] = 0ull;

        #pragma unroll 2
        for (int kk = 0; kk < 50; kk++) {
            const int k = kbeg + kk;
            const ulonglong2 w01 = *(const ulonglong2*)(Wp + k * 200 + hp * 4);
            const ulonglong2 w23 = *(const ulonglong2*)(Wp + k * 200 + hp * 4 + 2);
            const float4 h0 = *(const float4*)(hcur + k * 32 + bg * 8);
            const float4 h1 = *(const float4*)(hcur + k * 32 + bg * 8 + 4);
            u64 hd[8];
            hd[0] = pk(h0.x, h0.x); hd[1] = pk(h0.y, h0.y);
            hd[2] = pk(h0.z, h0.z); hd[3] = pk(h0.w, h0.w);
            hd[4] = pk(h1.x, h1.x); hd[5] = pk(h1.y, h1.y);
            hd[6] = pk(h1.z, h1.z); hd[7] = pk(h1.w, h1.w);
            #pragma unroll
            for (int b = 0; b < 8; b++) {
                fma2(acc[0][b], w01.x, hd[b]);
                fma2(acc[1][b], w01.y, hd[b]);
                fma2(acc[2][b], w23.x, hd[b]);
                fma2(acc[3][b], w23.y, hd[b]);
            }
        }

        // ---- partial-sum exchange (epilogue split by batch) ----
        // leg 1: g1 ships its b0..3 partials; g0 sums them.
        if (g) {
            #pragma unroll
            for (int q = 0; q < 8; q++) {
                int ty = q >> 1, b0 = (q & 1) * 2;
                ulonglong2 v; v.x = acc[ty][b0]; v.y = acc[ty][b0 + 1];
                *(ulonglong2*)(Rbuf + q * 400 + wtid * 2) = v;
            }
        }
        __syncthreads();
        if (!g) {
            #pragma unroll
            for (int q = 0; q < 8; q++) {
                int ty = q >> 1, b0 = (q & 1) * 2;
                ulonglong2 v = *(const ulonglong2*)(Rbuf + q * 400 + wtid * 2);
                add2(acc[ty][b0], v.x);
                add2(acc[ty][b0 + 1], v.y);
            }
            // leg 2: g0 ships its b4..7 partials into the same slots.
            #pragma unroll
            for (int q = 0; q < 8; q++) {
                int ty = q >> 1, b0 = 4 + (q & 1) * 2;
                ulonglong2 v; v.x = acc[ty][b0]; v.y = acc[ty][b0 + 1];
                *(ulonglong2*)(Rbuf + q * 400 + wtid * 2) = v;
            }
        }
        __syncthreads();
        if (g) {
            #pragma unroll
            for (int q = 0; q < 8; q++) {
                int ty = q >> 1, b0 = 4 + (q & 1) * 2;
                ulonglong2 v = *(const ulonglong2*)(Rbuf + q * 400 + wtid * 2);
                add2(acc[ty][b0], v.x);
                add2(acc[ty][b0 + 1], v.y);
            }
        }

        // ---- epilogue: my 4 batches (g0: b0..3, g1: b4..7 of the octet) ----
        float hn[2][4];
        #pragma unroll
        for (int j = 0; j < 4; j++) {
            int b = g * 4 + j;
            float xb = (j == 0) ? xv.x : (j == 1) ? xv.y : (j == 2) ? xv.z : xv.w;
            float2 gI = upk(acc[0][b]);
            float2 gF = upk(acc[1][b]);
            float2 gG = upk(acc[2][b]);
            float2 gO = upk(acc[3][b]);
            #pragma unroll
            for (int u = 0; u < 2; u++) {
                float vi = (u ? gI.y : gI.x) + fmaf(wi[u][0], xb, bs[u][0]);
                float vf = (u ? gF.y : gF.x) + fmaf(wi[u][1], xb, bs[u][1]);
                float vg = (u ? gG.y : gG.x) + fmaf(wi[u][2], xb, bs[u][2]);
                float vo = (u ? gO.y : gO.x) + fmaf(wi[u][3], xb, bs[u][3]);
                float si = sig_mufu(vi);
                float sf = sig_mufu(vf);
                float so = sig_mufu(vo);
                float tg = tanh_mufu(vg);
                float cn = fmaf(sf, c[u][j], si * tg);
                c[u][j] = cn;
                hn[u][j] = so * tanh_mufu(cn);
            }
        }
        #pragma unroll
        for (int u = 0; u < 2; u++) {
            int hu = 2 * hp + u;
            *(float4*)(hnxt + hu * 32 + bg * 8 + g * 4) =
                make_float4(hn[u][0], hn[u][1], hn[u][2], hn[u][3]);
        }
        __syncthreads();
    }

    // ---- linear head: out[b] = h_T[b] . W_lin + b_lin ----
    if (tid < TB) {
        const float* hfin = Hd;  // SEQ even -> final state in buffer 0
        float acc = blin[0];
        #pragma unroll 4
        for (int k = 0; k < H; k++)
            acc = fmaf(hfin[k * 32 + tid], __ldg(Wlin + k), acc);
        out[blockIdx.x * TB + tid] = acc;
    }
}

extern "C" void kernel_launch(void* const* d_in, const int* in_sizes, int n_in,
                              void* d_out, int out_size) {
    const float* x    = (const float*)d_in[0];
    const float* Wih  = (const float*)d_in[1];
    const float* Whh  = (const float*)d_in[2];
    const float* bih  = (const float*)d_in[3];
    const float* bhh  = (const float*)d_in[4];
    const float* Wlin = (const float*)d_in[5];
    const float* blin = (const float*)d_in[6];

    cudaFuncSetAttribute(lstm_kernel, cudaFuncAttributeMaxDynamicSharedMemorySize, SMEM_BYTES);
    lstm_kernel<<<NBLK, NTHREADS, SMEM_BYTES>>>(x, Wih, Whh, bih, bhh, Wlin, blin,
                                                (float*)d_out);
}

// round 7
// speedup vs baseline: 1.1905x; 1.1905x over previous
#include <cuda_runtime.h>
#include <cstdint>

#define H      100
#define NBATCH 4096
#define SEQ    512
#define TB     32
#define NBLK   (NBATCH / TB)   // 128
#define NTHREADS 400           // 50 hp-groups * 8 batch-groups (12.5 warps)

// smem (u64 units):
//   Wp [100][200] u64 : Wp[k*200 + hp*4 + ty] = (W[ty*100+2hp][k], W[ty*100+2hp+1][k])
//   Hd 2 x 3200 f32   : h[k][32] plain floats, double buffered
#define WP_U64 (100 * 200)     // 20000 u64 = 160,000 B
#define HD_F   (100 * 32)      // 3200 floats per buffer
#define SMEM_BYTES (WP_U64 * 8 + 2 * HD_F * 4)  // 185,600 B

typedef unsigned long long u64;

__device__ __forceinline__ void fma2(u64 &d, u64 a, u64 b) {
    asm("fma.rn.f32x2 %0, %1, %2, %0;" : "+l"(d) : "l"(a), "l"(b));
}
__device__ __forceinline__ u64 pk(float x, float y) {
    u64 r; asm("mov.b64 %0, {%1, %2};" : "=l"(r) : "f"(x), "f"(y)); return r;
}
__device__ __forceinline__ float2 upk(u64 v) {
    float2 r; asm("mov.b64 {%0, %1}, %2;" : "=f"(r.x), "=f"(r.y) : "l"(v)); return r;
}
__device__ __forceinline__ float tanh_mufu(float v) {
    float r; asm("tanh.approx.f32 %0, %1;" : "=f"(r) : "f"(v)); return r;
}
__device__ __forceinline__ float sig_mufu(float v) {
    return fmaf(0.5f, tanh_mufu(0.5f * v), 0.5f);
}

__global__ void __launch_bounds__(NTHREADS, 1)
lstm_kernel(const float* __restrict__ x,     // [512][4096]
            const float* __restrict__ Wih,   // [400]
            const float* __restrict__ Whh,   // [400][100]
            const float* __restrict__ bih,   // [400]
            const float* __restrict__ bhh,   // [400]
            const float* __restrict__ Wlin,  // [100]
            const float* __restrict__ blin,  // [1]
            float* __restrict__ out)         // [4096]
{
    extern __shared__ u64 sm[];
    u64*   Wp = sm;                       // [k*200 + hp*4 + ty]
    float* Hd = (float*)(sm + WP_U64);    // [buf*HD_F + k*32 + b]

    const int tid = threadIdx.x;
    const int hp  = tid >> 3;   // 0..49  (hidden pair: hu 2hp, 2hp+1)
    const int bg  = tid & 7;    // 0..7   (batch quad: batches bg*4 .. bg*4+3)

    // ---- Stage W_hh: pairs over adjacent hidden units, per gate type ----
    for (int idx = tid; idx < WP_U64; idx += NTHREADS) {
        int k  = idx / 200;
        int q  = idx % 200;
        int ph = q >> 2;
        int ty = q & 3;
        int row0 = ty * 100 + 2 * ph;
        Wp[idx] = pk(Whh[row0 * 100 + k], Whh[(row0 + 1) * 100 + k]);
    }
    // zero both h buffers (h0 = 0)
    for (int idx = tid; idx < 2 * HD_F; idx += NTHREADS)
        Hd[idx] = 0.f;

    // ---- per-thread constants: bias sums + W_ih for my 8 gate rows ----
    float bs[2][4], wi[2][4];  // [u][ty], types: 0=i 1=f 2=g 3=o
    #pragma unroll
    for (int u = 0; u < 2; u++) {
        int hu = 2 * hp + u;
        #pragma unroll
        for (int ty = 0; ty < 4; ty++) {
            int j = ty * 100 + hu;
            bs[u][ty] = bih[j] + bhh[j];
            wi[u][ty] = Wih[j];
        }
    }
    float c[2][4];  // cell state [u][b]
    #pragma unroll
    for (int u = 0; u < 2; u++)
        #pragma unroll
        for (int b = 0; b < 4; b++) c[u][b] = 0.f;

    const int bbase = blockIdx.x * TB + bg * 4;  // my 4 batches
    __syncthreads();

    // ---- recurrence over 512 steps ----
    for (int t = 0; t < SEQ; t++) {
        const float* hcur = Hd + ((t & 1) ? HD_F : 0);
        float*       hnxt = Hd + ((t & 1) ? 0 : HD_F);

        // x for my 4 batches (consumed only in epilogue -> latency hidden)
        float4 xv = *(const float4*)(x + (size_t)t * NBATCH + bbase);

        u64 acc[4][4];  // acc[ty][b] = f32x2 over (hu 2hp, 2hp+1)
        #pragma unroll
        for (int ty = 0; ty < 4; ty++)
            #pragma unroll
            for (int b = 0; b < 4; b++) acc[ty][b] = 0ull;

        #pragma unroll 2
        for (int k = 0; k < H; k++) {
            const ulonglong2 w01 = *(const ulonglong2*)(Wp + k * 200 + hp * 4);      // ty 0,1
            const ulonglong2 w23 = *(const ulonglong2*)(Wp + k * 200 + hp * 4 + 2);  // ty 2,3
            const float4 h0 = *(const float4*)(hcur + k * 32 + bg * 4);
            u64 hd[4];
            hd[0] = pk(h0.x, h0.x); hd[1] = pk(h0.y, h0.y);
            hd[2] = pk(h0.z, h0.z); hd[3] = pk(h0.w, h0.w);
            #pragma unroll
            for (int b = 0; b < 4; b++) {
                fma2(acc[0][b], w01.x, hd[b]);
                fma2(acc[1][b], w01.y, hd[b]);
                fma2(acc[2][b], w23.x, hd[b]);
                fma2(acc[3][b], w23.y, hd[b]);
            }
        }

        // ---- epilogue: gates -> activations -> c,h update ----
        float hn[2][4];
        #pragma unroll
        for (int b = 0; b < 4; b++) {
            float xb = (b == 0) ? xv.x : (b == 1) ? xv.y : (b == 2) ? xv.z : xv.w;
            float2 gI = upk(acc[0][b]);
            float2 gF = upk(acc[1][b]);
            float2 gG = upk(acc[2][b]);
            float2 gO = upk(acc[3][b]);
            #pragma unroll
            for (int u = 0; u < 2; u++) {
                float vi = (u ? gI.y : gI.x) + fmaf(wi[u][0], xb, bs[u][0]);
                float vf = (u ? gF.y : gF.x) + fmaf(wi[u][1], xb, bs[u][1]);
                float vg = (u ? gG.y : gG.x) + fmaf(wi[u][2], xb, bs[u][2]);
                float vo = (u ? gO.y : gO.x) + fmaf(wi[u][3], xb, bs[u][3]);
                float si = sig_mufu(vi);
                float sf = sig_mufu(vf);
                float so = sig_mufu(vo);
                float tg = tanh_mufu(vg);
                float cn = fmaf(sf, c[u][b], si * tg);
                c[u][b] = cn;
                hn[u][b] = so * tanh_mufu(cn);
            }
        }
        // vectorized h store
        #pragma unroll
        for (int u = 0; u < 2; u++) {
            int hu = 2 * hp + u;
            *(float4*)(hnxt + hu * 32 + bg * 4) =
                make_float4(hn[u][0], hn[u][1], hn[u][2], hn[u][3]);
        }
        __syncthreads();
    }

    // ---- linear head: out[b] = h_T[b] . W_lin + b_lin ----
    if (tid < TB) {
        const float* hfin = Hd;  // SEQ even -> final state in buffer 0
        float acc = blin[0];
        #pragma unroll 4
        for (int k = 0; k < H; k++)
            acc = fmaf(hfin[k * 32 + tid], __ldg(Wlin + k), acc);
        out[blockIdx.x * TB + tid] = acc;
    }
}

extern "C" void kernel_launch(void* const* d_in, const int* in_sizes, int n_in,
                              void* d_out, int out_size) {
    const float* x    = (const float*)d_in[0];
    const float* Wih  = (const float*)d_in[1];
    const float* Whh  = (const float*)d_in[2];
    const float* bih  = (const float*)d_in[3];
    const float* bhh  = (const float*)d_in[4];
    const float* Wlin = (const float*)d_in[5];
    const float* blin = (const float*)d_in[6];

    cudaFuncSetAttribute(lstm_kernel, cudaFuncAttributeMaxDynamicSharedMemorySize, SMEM_BYTES);
    lstm_kernel<<<NBLK, NTHREADS, SMEM_BYTES>>>(x, Wih, Whh, bih, bhh, Wlin, blin,
                                                (float*)d_out);
}